// round 3
// baseline (speedup 1.0000x reference)
#include <cuda_runtime.h>
#include <cuda_fp16.h>
#include <stdint.h>

#define FDIM      1024
#define BATCH     256
#define NCLS      1000
#define KTOT      65536
#define NTILES    8        // N tiles of 128 (1024 padded)
#define KSLICES   8
#define KPERSLICE 8192
#define NCHUNK    128      // 8192 / 64

// ---------------- static device scratch ----------------
__device__ __half g_A[(size_t)BATCH * KTOT];                 // 32 MB f16 basis [b][k]
__device__ float  g_part[(size_t)KSLICES * BATCH * 1024];    // 8 MB partials [sl][b][c]
__device__ float  g_rspart[KSLICES * 1024];                  // [sl][c]

// ---------------- helpers ----------------
__device__ __forceinline__ uint32_t smem_u32(const void* p) {
    uint32_t a;
    asm("{ .reg .u64 t; cvta.to.shared.u64 t, %1; cvt.u32.u64 %0, t; }" : "=r"(a) : "l"(p));
    return a;
}
__device__ __forceinline__ void ldsm_x4(uint32_t* r, uint32_t addr) {
    asm volatile("ldmatrix.sync.aligned.m8n8.x4.shared.b16 {%0,%1,%2,%3}, [%4];"
                 : "=r"(r[0]), "=r"(r[1]), "=r"(r[2]), "=r"(r[3]) : "r"(addr));
}
__device__ __forceinline__ void mma16816(float* d, const uint32_t* a, const uint32_t* b) {
    asm volatile(
        "mma.sync.aligned.m16n8k16.row.col.f32.f16.f16.f32 "
        "{%0,%1,%2,%3}, {%4,%5,%6,%7}, {%8,%9}, {%0,%1,%2,%3};"
        : "+f"(d[0]), "+f"(d[1]), "+f"(d[2]), "+f"(d[3])
        : "r"(a[0]), "r"(a[1]), "r"(a[2]), "r"(a[3]), "r"(b[0]), "r"(b[1]));
}
__device__ __forceinline__ void cp16(uint32_t dst, const void* src) {
    uint64_t g = (uint64_t)__cvta_generic_to_global(src);
    asm volatile("cp.async.cg.shared.global [%0], [%1], 16;" :: "r"(dst), "l"(g) : "memory");
}

// smem layout: padded rows of 144 B (64 halves + 8 pad halves)
#define ROWB   144
#define TILEB  (128 * ROWB)          // 18432
#define SM_A0  0
#define SM_B0  (2 * TILEB)           // 36864
#define SMEM_DYN (4 * TILEB + 16)    // 73744

// ---------------- Kernel 1: build dense f16 basis A[b][k] ----------------
__global__ void __launch_bounds__(256) embed_k(const float* __restrict__ x,
                                               const float* __restrict__ mn,
                                               const float* __restrict__ mx) {
    __shared__ uint32_t st[256 * 33];
    const int tid = threadIdx.x;
    const int b  = blockIdx.x >> 2;
    const int fc = blockIdx.x & 3;
    const int f  = fc * 256 + tid;

    const float mnv = mn[0], mxv = mx[0];
    const float xn = (x[b * FDIM + f] - mnv) / (mxv - mnv);
    const float h  = 1.0f / 63.0f;
    const float s  = xn / h;

    uint32_t* myst = st + tid * 33;
    #pragma unroll
    for (int w = 0; w < 32; w++) myst[w] = 0u;

    if (s >= 0.0f && s <= 63.0f) {
        int t = (int)floorf(s);
        if (t > 62) t = 62;
        float lam0 = s - (float)t;          // -> vertex t+1
        float lam1 = (float)(t + 1) - s;    // -> vertex t
        myst[t >> 1] |= (uint32_t)__half_as_ushort(__float2half_rn(lam1)) << ((t & 1) * 16);
        int t1 = t + 1;
        myst[t1 >> 1] |= (uint32_t)__half_as_ushort(__float2half_rn(lam0)) << ((t1 & 1) * 16);
    }
    __syncthreads();

    uint32_t* gA = (uint32_t*)g_A + (size_t)b * (KTOT / 2) + (size_t)fc * 8192;
    #pragma unroll
    for (int j = 0; j < 32; j++) {
        int idx = j * 256 + tid;
        gA[idx] = st[idx + (idx >> 5)];   // f_local*33 + word
    }
}

// ---------------- Kernel 2: HMMA GEMM partial + W rowsum ----------------
__global__ void __launch_bounds__(256, 1) gemm_k(const float* __restrict__ W) {
    extern __shared__ char smraw[];
    const uint32_t sb = smem_u32(smraw);

    const int tid = threadIdx.x;
    const int wid = tid >> 5;
    const int lane = tid & 31;
    const int mt = blockIdx.x & 1;          // M half (0/1), adjacent CTAs share W via L2
    const int nt = blockIdx.x >> 1;         // 0..7
    const int sl = blockIdx.y;              // 0..7
    const int m0 = mt * 128;
    const int n0 = nt * 128;

    // warp tile: wm in {0,32,64,96}, wn in {0,64}
    const int wm = (wid & 3) * 32;
    const int wn = (wid >> 2) * 64;

    // ---- B loader role: thread -> (class row n, 32-k half) ----
    const int nrow = tid >> 1;
    const int khalf = tid & 1;
    int cls = n0 + nrow; if (cls > NCLS - 1) cls = NCLS - 1;
    const float* wsrc = W + (size_t)cls * KTOT + (size_t)sl * KPERSLICE + khalf * 32;
    // ---- A loader role: thread -> (batch row, 32-k half) ----
    const __half* asrc = g_A + (size_t)(m0 + nrow) * KTOT + (size_t)sl * KPERSLICE + khalf * 32;

    float d[2][8][4];
    #pragma unroll
    for (int i = 0; i < 2; i++)
        #pragma unroll
        for (int j = 0; j < 8; j++)
            #pragma unroll
            for (int q = 0; q < 4; q++) d[i][j][q] = 0.f;

    float rs = 0.f;
    float4 v[8];

    const uint32_t aDstBase = sb + SM_A0 + (uint32_t)nrow * ROWB + (uint32_t)khalf * 64u;
    const uint32_t bDstBase = sb + SM_B0 + (uint32_t)nrow * ROWB + (uint32_t)khalf * 64u;

    // prologue: chunk 0
    {
        #pragma unroll
        for (int q = 0; q < 4; q++) cp16(aDstBase + q * 16u, asrc + q * 8);
        asm volatile("cp.async.commit_group;" ::: "memory");
        const float4* wg = (const float4*)wsrc;
        #pragma unroll
        for (int j = 0; j < 8; j++) v[j] = wg[j];
        #pragma unroll
        for (int j = 0; j < 8; j++) {
            rs += v[j].x + v[j].y + v[j].z + v[j].w;
            __half2 h0 = __floats2half2_rn(v[j].x, v[j].y);
            __half2 h1 = __floats2half2_rn(v[j].z, v[j].w);
            asm volatile("st.shared.v2.u32 [%0], {%1, %2};"
                         :: "r"(bDstBase + j * 8u), "r"(*(uint32_t*)&h0), "r"(*(uint32_t*)&h1) : "memory");
        }
        asm volatile("cp.async.wait_group 0;" ::: "memory");
        __syncthreads();
    }

    for (int c = 0; c < NCHUNK; c++) {
        const int buf = c & 1;
        const bool hasNext = (c + 1 < NCHUNK);

        if (hasNext) {
            const uint32_t nb = buf ^ 1;
            #pragma unroll
            for (int q = 0; q < 4; q++)
                cp16(aDstBase + nb * TILEB + q * 16u, asrc + (size_t)(c + 1) * 64 + q * 8);
            asm volatile("cp.async.commit_group;" ::: "memory");
            const float4* wg = (const float4*)(wsrc + (size_t)(c + 1) * 64);
            #pragma unroll
            for (int j = 0; j < 8; j++) v[j] = wg[j];
        }

        // ---- compute current buffer: 4 k-steps of 16 ----
        const uint32_t aBuf = sb + SM_A0 + (uint32_t)buf * TILEB;
        const uint32_t bBuf = sb + SM_B0 + (uint32_t)buf * TILEB;
        #pragma unroll
        for (int ks = 0; ks < 4; ks++) {
            uint32_t a[2][4];
            #pragma unroll
            for (int mi = 0; mi < 2; mi++) {
                uint32_t row = (uint32_t)(wm + mi * 16 + (lane & 15));
                uint32_t kb  = (uint32_t)(ks * 32 + (lane >> 4) * 16);
                ldsm_x4(a[mi], aBuf + row * ROWB + kb);
            }
            uint32_t b[4][4];
            #pragma unroll
            for (int nj = 0; nj < 4; nj++) {
                uint32_t row = (uint32_t)(wn + nj * 16 + (lane & 7) + (lane >> 4) * 8);
                uint32_t kb  = (uint32_t)(ks * 32 + ((lane >> 3) & 1) * 16);
                ldsm_x4(b[nj], bBuf + row * ROWB + kb);
            }
            #pragma unroll
            for (int mi = 0; mi < 2; mi++)
                #pragma unroll
                for (int nj = 0; nj < 4; nj++) {
                    mma16816(d[mi][nj * 2 + 0], a[mi], &b[nj][0]);
                    mma16816(d[mi][nj * 2 + 1], a[mi], &b[nj][2]);
                }
        }

        if (hasNext) {
            const uint32_t nb = buf ^ 1;
            #pragma unroll
            for (int j = 0; j < 8; j++) {
                rs += v[j].x + v[j].y + v[j].z + v[j].w;
                __half2 h0 = __floats2half2_rn(v[j].x, v[j].y);
                __half2 h1 = __floats2half2_rn(v[j].z, v[j].w);
                asm volatile("st.shared.v2.u32 [%0], {%1, %2};"
                             :: "r"(bDstBase + nb * TILEB + j * 8u),
                                "r"(*(uint32_t*)&h0), "r"(*(uint32_t*)&h1) : "memory");
            }
            asm volatile("cp.async.wait_group 0;" ::: "memory");
        }
        __syncthreads();
    }

    // ---- rowsum partial (pair of threads per class row; mt==0 CTA writes) ----
    float tot = rs + __shfl_xor_sync(0xffffffffu, rs, 1);
    if (khalf == 0 && mt == 0) g_rspart[sl * 1024 + n0 + nrow] = tot;

    // ---- store accumulators to g_part[sl][b][c] ----
    float* base = g_part + (size_t)sl * BATCH * 1024;
    #pragma unroll
    for (int mi = 0; mi < 2; mi++) {
        #pragma unroll
        for (int nj = 0; nj < 8; nj++) {
            int bb = m0 + wm + mi * 16 + (lane >> 2);
            int cc = n0 + wn + nj * 8 + (lane & 3) * 2;
            float2* p0 = (float2*)(base + (size_t)bb * 1024 + cc);
            *p0 = make_float2(d[mi][nj][0], d[mi][nj][1]);
            float2* p1 = (float2*)(base + (size_t)(bb + 8) * 1024 + cc);
            *p1 = make_float2(d[mi][nj][2], d[mi][nj][3]);
        }
    }
}

// ---------------- Kernel 3: reduce + rowsum term ----------------
__global__ void __launch_bounds__(256) epi_k(const float* __restrict__ mn,
                                             const float* __restrict__ mx,
                                             float* __restrict__ out) {
    const int b = blockIdx.x;        // 0..255
    const float mnv = mn[0], mxv = mx[0];
    const float sc = mxv - mnv;
    for (int c = threadIdx.x; c < NCLS; c += 256) {
        float s = 0.f, rsum = 0.f;
        #pragma unroll
        for (int sl = 0; sl < KSLICES; sl++) {
            s += g_part[((size_t)sl * BATCH + b) * 1024 + c];
            rsum += g_rspart[sl * 1024 + c];
        }
        out[(size_t)b * NCLS + c] = sc * s + mnv * rsum;
    }
}

// ---------------- launch ----------------
extern "C" void kernel_launch(void* const* d_in, const int* in_sizes, int n_in,
                              void* d_out, int out_size) {
    const float* x  = (const float*)d_in[0];
    const float* mn = (const float*)d_in[1];
    const float* mx = (const float*)d_in[2];
    const float* W  = (const float*)d_in[3];
    float* out = (float*)d_out;

    embed_k<<<1024, 256>>>(x, mn, mx);

    cudaFuncSetAttribute(gemm_k, cudaFuncAttributeMaxDynamicSharedMemorySize, SMEM_DYN);
    gemm_k<<<dim3(16, KSLICES), 256, SMEM_DYN>>>(W);

    epi_k<<<BATCH, 256>>>(mn, mx, out);
}

// round 4
// speedup vs baseline: 2.0507x; 2.0507x over previous
#include <cuda_runtime.h>
#include <cuda_fp16.h>
#include <stdint.h>

#define FDIM      1024
#define BATCH     256
#define NCLS      1000
#define CPAD      1024
#define KROW      65536        // F*DOF per W row
#define CB        8            // class blocks of 128
#define FS        16           // f slices of 64
#define F_PER_CTA 64
#define THREADS   512

// ---------------- static device scratch ----------------
__device__ uint2 g_meta[FDIM * BATCH];                 // [f][b]: {t*4 bytes, half2(lam1,lam0)}
__device__ float g_part[(size_t)FS * BATCH * CPAD];    // [fs][b][c]
__device__ float g_rspart[FS * CPAD];                  // [fs][c]

// ---------------- Kernel 1: per-(b,f) barycentric meta ----------------
__global__ void __launch_bounds__(256) embed_k(const float* __restrict__ x,
                                               const float* __restrict__ mn,
                                               const float* __restrict__ mx) {
    const int idx = blockIdx.x * 256 + threadIdx.x;    // idx = b*FDIM + f (coalesced x read)
    const int b = idx >> 10;
    const int f = idx & 1023;
    const float mnv = mn[0], mxv = mx[0];
    const float s = (x[idx] - mnv) / (mxv - mnv) * 63.0f;
    const bool valid = (s >= 0.0f) && (s <= 63.0f);
    int t = (int)s;
    if (t > 62) t = 62;
    if (t < 0)  t = 0;
    const float lam0 = valid ? (s - (float)t) : 0.0f;        // -> vertex t+1
    const float lam1 = valid ? ((float)(t + 1) - s) : 0.0f;  // -> vertex t
    __half2 h = __floats2half2_rn(lam1, lam0);
    uint2 m;
    m.x = (uint32_t)t * 4u;          // byte offset into stride-65 float row
    m.y = *(uint32_t*)&h;
    g_meta[f * BATCH + b] = m;
}

// ---------------- Kernel 2: smem-broadcast sparse gather ----------------
// CTA: 128 classes (cb) x 64 f (fs) x all 256 b.
// lane -> 4 classes (lane, lane+32, lane+64, lane+96); warp -> 16 b's.
// smem W tile: [cls][65] floats, double buffered. All lanes share t => conflict-free LDS.
__global__ void __launch_bounds__(THREADS, 1) gather_k(const float* __restrict__ W) {
    extern __shared__ float sm[];                      // 2 * 128*65 floats
    float* bufs[2] = { sm, sm + 128 * 65 };

    const int tid  = threadIdx.x;
    const int lane = tid & 31;
    const int w    = tid >> 5;          // 0..15
    const int cb   = blockIdx.x;        // 0..7
    const int fs   = blockIdx.y;        // 0..15
    const int fbase = fs * F_PER_CTA;

    // ---- fill role: pass p -> class row pass*32 + w*2 + (lane>>4), cols (lane&15)*4 .. +4
    int rowl[4];
    const float* wptr[4];
    #pragma unroll
    for (int p = 0; p < 4; p++) {
        const int cl = p * 32 + w * 2 + (lane >> 4);
        rowl[p] = cl;
        int cls = cb * 128 + cl;
        if (cls > NCLS - 1) cls = NCLS - 1;            // clamp (rows >=1000 never read back)
        wptr[p] = W + (size_t)cls * KROW + (size_t)fbase * 64 + (lane & 15) * 4;
    }

    float acc[4][16];
    #pragma unroll
    for (int k = 0; k < 4; k++)
        #pragma unroll
        for (int j = 0; j < 16; j++) acc[k][j] = 0.0f;
    float rs[4] = {0.f, 0.f, 0.f, 0.f};

    // prologue: prefetch f0 W tile + meta
    float4 wv[4];
    #pragma unroll
    for (int p = 0; p < 4; p++) wv[p] = *(const float4*)(wptr[p]);
    uint2 mcur = make_uint2(0u, 0u);
    if (lane < 16) mcur = g_meta[fbase * BATCH + w * 16 + lane];

    for (int fi = 0; fi < F_PER_CTA; fi++) {
        float* buf = bufs[fi & 1];

        // store W tile from regs + inline rowsum
        #pragma unroll
        for (int p = 0; p < 4; p++) {
            const float4 v = wv[p];
            rs[p] += (v.x + v.y) + (v.z + v.w);
            float* dst = buf + rowl[p] * 65 + (lane & 15) * 4;
            dst[0] = v.x; dst[1] = v.y; dst[2] = v.z; dst[3] = v.w;
        }
        __syncthreads();   // single barrier per f (double buffer makes cross-iter writes safe)

        const uint2 m = mcur;

        // prefetch next f (regs) — hidden under the gather below
        if (fi + 1 < F_PER_CTA) {
            #pragma unroll
            for (int p = 0; p < 4; p++)
                wv[p] = *(const float4*)(wptr[p] + (size_t)(fi + 1) * 64);
            if (lane < 16)
                mcur = g_meta[(fbase + fi + 1) * BATCH + w * 16 + lane];
        }

        // gather: 16 b's, broadcast (toff, lams), 4 classes per lane
        const char* lanebase = (const char*)(buf + lane * 65);
        #pragma unroll
        for (int j = 0; j < 16; j++) {
            const uint32_t toff = __shfl_sync(0xffffffffu, m.x, j);
            const uint32_t lmu  = __shfl_sync(0xffffffffu, m.y, j);
            const __half2 lh = *(const __half2*)&lmu;
            const float2 lm = __half22float2(lh);      // x = lam1 (@t), y = lam0 (@t+1)
            const float* pb = (const float*)(lanebase + toff);
            #pragma unroll
            for (int k = 0; k < 4; k++) {
                const float w0 = pb[k * 32 * 65];
                const float w1 = pb[k * 32 * 65 + 1];
                acc[k][j] = fmaf(lm.x, w0, fmaf(lm.y, w1, acc[k][j]));
            }
        }
    }

    // ---- rowsum partials: reduce 16 col-lanes per class row ----
    #pragma unroll
    for (int p = 0; p < 4; p++) {
        float r = rs[p];
        r += __shfl_xor_sync(0xffffffffu, r, 1);
        r += __shfl_xor_sync(0xffffffffu, r, 2);
        r += __shfl_xor_sync(0xffffffffu, r, 4);
        r += __shfl_xor_sync(0xffffffffu, r, 8);
        if ((lane & 15) == 0)
            g_rspart[fs * CPAD + cb * 128 + rowl[p]] = r;
    }

    // ---- store GEMM partials: [fs][b][c], coalesced 128B per STG ----
    #pragma unroll
    for (int j = 0; j < 16; j++) {
        const int b = w * 16 + j;
        float* pp = g_part + ((size_t)fs * BATCH + b) * CPAD + cb * 128;
        #pragma unroll
        for (int k = 0; k < 4; k++) pp[k * 32 + lane] = acc[k][j];
    }
}

// ---------------- Kernel 3: reduce partials + rowsum term ----------------
__global__ void __launch_bounds__(256) epi_k(const float* __restrict__ mn,
                                             const float* __restrict__ mx,
                                             float* __restrict__ out) {
    const int b = blockIdx.x;            // 0..255
    const float mnv = mn[0], mxv = mx[0];
    const float sc = mxv - mnv;
    for (int c = threadIdx.x; c < NCLS; c += 256) {
        float s = 0.f, rsum = 0.f;
        #pragma unroll
        for (int fsl = 0; fsl < FS; fsl++) {
            s    += g_part[((size_t)fsl * BATCH + b) * CPAD + c];
            rsum += g_rspart[fsl * CPAD + c];
        }
        out[(size_t)b * NCLS + c] = sc * s + mnv * rsum;
    }
}

// ---------------- launch ----------------
extern "C" void kernel_launch(void* const* d_in, const int* in_sizes, int n_in,
                              void* d_out, int out_size) {
    const float* x  = (const float*)d_in[0];
    const float* mn = (const float*)d_in[1];
    const float* mx = (const float*)d_in[2];
    const float* W  = (const float*)d_in[3];
    float* out = (float*)d_out;

    embed_k<<<1024, 256>>>(x, mn, mx);

    const int smem = 2 * 128 * 65 * (int)sizeof(float);   // 66560 B
    cudaFuncSetAttribute(gather_k, cudaFuncAttributeMaxDynamicSharedMemorySize, smem);
    gather_k<<<dim3(CB, FS), THREADS, smem>>>(W);

    epi_k<<<BATCH, 256>>>(mn, mx, out);
}